// round 7
// baseline (speedup 1.0000x reference)
#include <cuda_runtime.h>
#include <cuda_bf16.h>

// ---------------------------------------------------------------------------
// HilbertSerialization: 2M points -> 26-bit Hilbert+batch code -> stable argsort
// Output dtype: FLOAT32 (indices written as float values; all < 2^24, exact).
// Hand-rolled 3-pass stable LSD radix sort (9,9,8 bits); final pass scatters
// indices straight into d_out as float.
// All graph-capturable, zero allocations (static __device__ scratch).
// ---------------------------------------------------------------------------

#define HS_MAXN   2000000
#define TILE      4096
#define THREADS   128
#define MAXBINS   512
#define NBLK_MAX  ((HS_MAXN + TILE - 1) / TILE)   // 489

__device__ unsigned int g_keys_a[HS_MAXN];
__device__ unsigned int g_keys_b[HS_MAXN];
__device__ unsigned int g_vals_a[HS_MAXN];
__device__ unsigned int g_vals_b[HS_MAXN];
__device__ unsigned int g_counts[MAXBINS * NBLK_MAX];
__device__ unsigned int g_rowtot[MAXBINS];
__device__ unsigned int g_rowbase[MAXBINS];
__device__ int g_coords64;

// ---------------------------------------------------------------------------
// Encode
// ---------------------------------------------------------------------------
__global__ void detect_dtype_kernel(const unsigned int* __restrict__ w, int nwords)
{
    __shared__ int ok;
    if (threadIdx.x == 0) ok = 1;
    __syncthreads();
    for (int i = 2 * threadIdx.x + 1; i < nwords; i += 2 * blockDim.x) {
        if (w[i] != 0u) { ok = 0; break; }
    }
    __syncthreads();
    if (threadIdx.x == 0) g_coords64 = ok;
}

__global__ void __launch_bounds__(256)
hilbert_encode_kernel(const unsigned int* __restrict__ coords,
                      const unsigned int* __restrict__ ss,
                      const unsigned int* __restrict__ shifts,
                      unsigned int* __restrict__ keys,
                      unsigned int* __restrict__ vals,
                      int n)
{
    int i = blockIdx.x * blockDim.x + threadIdx.x;
    if (i >= n) return;

    unsigned int b, zc, yc, xc;                  // coords row = [b, z, y, x]
    if (g_coords64) {
        const unsigned int* p = coords + (size_t)i * 8;   // int64 stride
        b = p[0]; zc = p[2]; yc = p[4]; xc = p[6];
    } else {
        uint4 c = reinterpret_cast<const uint4*>(coords)[i];
        b = c.x; zc = c.y; yc = c.z; xc = c.w;
    }

    int D, H, W;                                 // sparse_shape = [D, H, W]
    if (ss[1] == 0u) { D = (int)ss[0]; H = (int)ss[2]; W = (int)ss[4]; }
    else             { D = (int)ss[0]; H = (int)ss[1]; W = (int)ss[2]; }

    bool sh = (shifts[0] != 0u);
    int sx = sh ? 15 : 0, sy = sh ? 15 : 0, sz = sh ? 4 : 0;

    unsigned int x = (unsigned int)(((int)xc + sx) % W);
    unsigned int y = (unsigned int)(((int)yc + sy) % H);
    unsigned int z = (unsigned int)(((int)zc + sz) % D);

    // LITERAL transcription of reference hilbert_encode.
    // locs = [x, y, z]; gray[dim][bit], bit index 0 = MSB (shifts_ = 7..0).
    bool gray[3][8];
    unsigned int loc[3] = { x, y, z };
    #pragma unroll
    for (int dim = 0; dim < 3; ++dim)
        #pragma unroll
        for (int bit = 0; bit < 8; ++bit)
            gray[dim][bit] = ((loc[dim] >> (7 - bit)) & 1u) != 0u;

    #pragma unroll
    for (int bit = 0; bit < 8; ++bit) {
        #pragma unroll
        for (int dim = 0; dim < 3; ++dim) {
            bool mask = gray[dim][bit];
            for (int j = bit + 1; j < 8; ++j)
                gray[0][j] = gray[0][j] != mask;
            for (int j = bit + 1; j < 8; ++j) {
                bool to_flip = (!mask) && (gray[0][j] != gray[dim][j]);
                gray[dim][j] = gray[dim][j] != to_flip;
                gray[0][j]   = gray[0][j]   != to_flip;
            }
        }
    }

    // bits[bit*3+dim] with weight 2^(23-idx): bit-major, dim-minor, MSB first.
    unsigned int h = 0;
    #pragma unroll
    for (int bit = 0; bit < 8; ++bit)
        #pragma unroll
        for (int dim = 0; dim < 3; ++dim)
            h = (h << 1) | (gray[dim][bit] ? 1u : 0u);

    // _gray2binary: prefix XOR stages (shift = 16,8,4,2,1).
    h ^= h >> 16; h ^= h >> 8; h ^= h >> 4; h ^= h >> 2; h ^= h >> 1;

    keys[i] = h | (b << 24);                     // code | b << DEPTH*3
    vals[i] = (unsigned int)i;
}

// ---------------------------------------------------------------------------
// Block exclusive scan utility (THREADS=128, 4 warps). ws must hold >=5 uints.
// ---------------------------------------------------------------------------
__device__ __forceinline__ unsigned int block_exscan(unsigned int v,
                                                     unsigned int* ws,
                                                     unsigned int* total)
{
    int lane = threadIdx.x & 31, wid = threadIdx.x >> 5;
    unsigned int inc = v;
    #pragma unroll
    for (int o = 1; o < 32; o <<= 1) {
        unsigned int u = __shfl_up_sync(~0u, inc, o);
        if (lane >= o) inc += u;
    }
    __syncthreads();
    if (lane == 31) ws[wid] = inc;
    __syncthreads();
    if (threadIdx.x == 0) {
        unsigned int s = 0;
        #pragma unroll
        for (int i = 0; i < 4; ++i) { unsigned int t = ws[i]; ws[i] = s; s += t; }
        ws[4] = s;
    }
    __syncthreads();
    if (total) *total = ws[4];
    return inc - v + ws[wid];
}

// ---------------------------------------------------------------------------
// Per-pass kernels
// ---------------------------------------------------------------------------
template<int SHIFT, int BITS>
__global__ void __launch_bounds__(THREADS)
histo_kernel(const unsigned int* __restrict__ keys,
             unsigned int* __restrict__ counts, int n, int nblocks)
{
    const int NBINS = 1 << BITS;
    __shared__ unsigned int h[NBINS];
    for (int i = threadIdx.x; i < NBINS; i += THREADS) h[i] = 0;
    __syncthreads();
    int start = blockIdx.x * TILE;
    for (int i = threadIdx.x; i < TILE; i += THREADS) {
        int g = start + i;
        if (g < n) atomicAdd(&h[(keys[g] >> SHIFT) & (NBINS - 1)], 1u);
    }
    __syncthreads();
    for (int i = threadIdx.x; i < NBINS; i += THREADS)
        counts[(size_t)i * nblocks + blockIdx.x] = h[i];
}

__global__ void __launch_bounds__(THREADS)
scan_rows_kernel(unsigned int* __restrict__ counts,
                 unsigned int* __restrict__ rowtot, int nblocks)
{
    __shared__ unsigned int ws[5];
    unsigned int* row = counts + (size_t)blockIdx.x * nblocks;
    int base = threadIdx.x * 4;
    unsigned int v[4], s = 0;
    #pragma unroll
    for (int j = 0; j < 4; ++j) {
        int i = base + j;
        v[j] = (i < nblocks) ? row[i] : 0u;
        s += v[j];
    }
    unsigned int total;
    unsigned int run = block_exscan(s, ws, &total);
    #pragma unroll
    for (int j = 0; j < 4; ++j) {
        int i = base + j;
        if (i < nblocks) row[i] = run;
        run += v[j];
    }
    if (threadIdx.x == 0) rowtot[blockIdx.x] = total;
}

__global__ void __launch_bounds__(THREADS)
scan_base_kernel(const unsigned int* __restrict__ rowtot,
                 unsigned int* __restrict__ rowbase, int nbins)
{
    __shared__ unsigned int ws[5];
    int base = threadIdx.x * 4;
    unsigned int v[4], s = 0;
    #pragma unroll
    for (int j = 0; j < 4; ++j) {
        int i = base + j;
        v[j] = (i < nbins) ? rowtot[i] : 0u;
        s += v[j];
    }
    unsigned int run = block_exscan(s, ws, 0);
    #pragma unroll
    for (int j = 0; j < 4; ++j) {
        int i = base + j;
        if (i < nbins) rowbase[i] = run;
        run += v[j];
    }
}

// Stable scatter: warp-match ranking, tile order = (warp, iter, lane).
// FINAL=1: write indices as FLOAT32 directly to outf, skip key write.
template<int SHIFT, int BITS, int FINAL>
__global__ void __launch_bounds__(THREADS)
scatter_kernel(const unsigned int* __restrict__ keys_in,
               const unsigned int* __restrict__ vals_in,
               unsigned int* __restrict__ keys_out,
               unsigned int* __restrict__ vals_out,
               float* __restrict__ outf,
               const unsigned int* __restrict__ counts,   // row-scanned
               const unsigned int* __restrict__ rowbase,
               int n, int nblocks)
{
    const int NBINS = 1 << BITS;
    const int IPT   = TILE / THREADS;              // 32
    __shared__ unsigned short cnt[NBINS][4];       // [digit][warp]
    __shared__ unsigned int dpref[NBINS];
    __shared__ unsigned int gbase[NBINS];
    __shared__ unsigned int skeys[TILE];
    __shared__ unsigned int svals[TILE];
    __shared__ unsigned int ws[5];

    int t = threadIdx.x, lane = t & 31, w = t >> 5;
    int start = blockIdx.x * TILE;

    for (int i = t; i < TILE; i += THREADS) {
        int g = start + i;
        if (g < n) { skeys[i] = keys_in[g]; svals[i] = vals_in[g]; }
    }
    unsigned int* cnt32 = (unsigned int*)&cnt[0][0];
    for (int i = t; i < NBINS * 2; i += THREADS) cnt32[i] = 0;
    for (int d = t; d < NBINS; d += THREADS)
        gbase[d] = counts[(size_t)d * nblocks + blockIdx.x] + rowbase[d];
    __syncthreads();

    // Phase 1: per-warp histogram.
    for (int k = 0; k < IPT; ++k) {
        int i = w * (32 * IPT) + k * 32 + lane;
        int g = start + i;
        bool act = (g < n);
        unsigned int amask = __ballot_sync(~0u, act);
        if (act) {
            unsigned int d = (skeys[i] >> SHIFT) & (NBINS - 1);
            unsigned int peers = __match_any_sync(amask, d);
            int leader = __ffs(peers) - 1;
            if (lane == leader)
                cnt[d][w] = (unsigned short)(cnt[d][w] + __popc(peers));
        }
    }
    __syncthreads();

    // Flat exclusive scan of cnt in (digit, warp) order.
    {
        unsigned short* flat = &cnt[0][0];
        const int E = (NBINS * 4) / THREADS;       // 16 (BITS=9) / 8 (BITS=8)
        unsigned int loc[16], s = 0;
        #pragma unroll
        for (int j = 0; j < E; ++j) { loc[j] = flat[t * E + j]; s += loc[j]; }
        unsigned int run = block_exscan(s, ws, 0);
        #pragma unroll
        for (int j = 0; j < E; ++j) {
            flat[t * E + j] = (unsigned short)run;
            run += loc[j];
        }
    }
    __syncthreads();
    for (int d = t; d < NBINS; d += THREADS) dpref[d] = cnt[d][0];
    __syncthreads();

    // Phase 2: rank (stable) + scatter.
    for (int k = 0; k < IPT; ++k) {
        int i = w * (32 * IPT) + k * 32 + lane;
        int g = start + i;
        bool act = (g < n);
        unsigned int amask = __ballot_sync(~0u, act);
        if (act) {
            unsigned int key = skeys[i];
            unsigned int d = (key >> SHIFT) & (NBINS - 1);
            unsigned int peers = __match_any_sync(amask, d);
            int leader = __ffs(peers) - 1;
            unsigned int base = 0;
            if (lane == leader) {
                base = cnt[d][w];
                cnt[d][w] = (unsigned short)(base + __popc(peers));
            }
            base = __shfl_sync(peers, base, leader);
            unsigned int rank = base + __popc(peers & ((1u << lane) - 1u));
            unsigned int pos = gbase[d] + rank - dpref[d];
            if (FINAL) {
                outf[pos] = (float)svals[i];       // FLOAT32 output dtype
            } else {
                keys_out[pos] = key;
                vals_out[pos] = svals[i];
            }
        }
    }
}

// ---------------------------------------------------------------------------
// Host
// ---------------------------------------------------------------------------
template<int SHIFT, int BITS, int FINAL>
static void radix_pass(const unsigned int* ki, const unsigned int* vi,
                       unsigned int* ko, unsigned int* vo, float* outf,
                       unsigned int* counts, unsigned int* rowtot,
                       unsigned int* rowbase, int n, int nblocks)
{
    const int NBINS = 1 << BITS;
    histo_kernel<SHIFT, BITS><<<nblocks, THREADS>>>(ki, counts, n, nblocks);
    scan_rows_kernel<<<NBINS, THREADS>>>(counts, rowtot, nblocks);
    scan_base_kernel<<<1, THREADS>>>(rowtot, rowbase, NBINS);
    scatter_kernel<SHIFT, BITS, FINAL><<<nblocks, THREADS>>>(
        ki, vi, ko, vo, outf, counts, rowbase, n, nblocks);
}

extern "C" void kernel_launch(void* const* d_in, const int* in_sizes, int n_in,
                              void* d_out, int out_size)
{
    // Identify inputs by size signature.
    int ci = 0;
    for (int i = 1; i < n_in; ++i)
        if (in_sizes[i] > in_sizes[ci]) ci = i;
    int si = -1, hi = -1;
    for (int i = 0; i < n_in; ++i) {
        if (i == ci) continue;
        if (si < 0) { si = i; continue; }
        if (hi < 0) { hi = i; continue; }
    }
    if (hi >= 0 && in_sizes[hi] > in_sizes[si]) { int tq = si; si = hi; hi = tq; }
    if (si < 0) si = ci;
    if (hi < 0) hi = si;

    const unsigned int* coords = (const unsigned int*)d_in[ci];
    const unsigned int* ss     = (const unsigned int*)d_in[si];
    const unsigned int* shifts = (const unsigned int*)d_in[hi];

    int n = out_size;
    if (n > HS_MAXN) n = HS_MAXN;
    if (n <= 0) return;

    unsigned int *ka, *kb, *va, *vb, *counts, *rowtot, *rowbase;
    cudaGetSymbolAddress((void**)&ka, g_keys_a);
    cudaGetSymbolAddress((void**)&kb, g_keys_b);
    cudaGetSymbolAddress((void**)&va, g_vals_a);
    cudaGetSymbolAddress((void**)&vb, g_vals_b);
    cudaGetSymbolAddress((void**)&counts, g_counts);
    cudaGetSymbolAddress((void**)&rowtot, g_rowtot);
    cudaGetSymbolAddress((void**)&rowbase, g_rowbase);

    detect_dtype_kernel<<<1, 256>>>(coords, 4096);

    int eblocks = (n + 255) / 256;
    hilbert_encode_kernel<<<eblocks, 256>>>(coords, ss, shifts, ka, va, n);

    int nblocks = (n + TILE - 1) / TILE;
    radix_pass<0,  9, 0>(ka, va, kb, vb, 0, counts, rowtot, rowbase, n, nblocks);
    radix_pass<9,  9, 0>(kb, vb, ka, va, 0, counts, rowtot, rowbase, n, nblocks);
    radix_pass<18, 8, 1>(ka, va, 0, 0, (float*)d_out,
                         counts, rowtot, rowbase, n, nblocks);
}